// round 3
// baseline (speedup 1.0000x reference)
#include <cuda_runtime.h>
#include <math.h>

// Problem constants
#define BB   64
#define NN   4096
#define IND  256
#define SS   8
#define DD   256
#define ROWS (BB*SS)        // 512
#define NCHUNK 8
#define NT   (NN/NCHUNK)    // 512 n's per chunk

// -------- scratch (device globals; no allocation allowed) --------
__device__ float g_slots [ROWS*DD];
__device__ float g_ln    [ROWS*DD];
__device__ float g_q     [ROWS*DD];
__device__ float g_qW    [ROWS*IND];
__device__ float g_attn  [BB*SS*NN];          // logits then attn in-place (8 MB)
__device__ float g_upart [NCHUNK*BB*SS*IND];  // 4 MB partials of attn@X
__device__ float g_upd   [ROWS*DD];
__device__ float g_gi    [ROWS*3*DD];
__device__ float g_gh    [ROWS*3*DD];
__device__ float g_hidden[ROWS*DD];

// -------- reductions --------
__device__ __forceinline__ float warpSum(float v){
#pragma unroll
    for (int o = 16; o > 0; o >>= 1) v += __shfl_xor_sync(0xffffffffu, v, o);
    return v;
}
__device__ __forceinline__ float warpMax(float v){
#pragma unroll
    for (int o = 16; o > 0; o >>= 1) v = fmaxf(v, __shfl_xor_sync(0xffffffffu, v, o));
    return v;
}

// -------- slots = mu + sigma * noise --------
__global__ void init_slots_kernel(const float* __restrict__ noise,
                                  const float* __restrict__ mu,
                                  const float* __restrict__ sigma,
                                  float* __restrict__ slots){
    int i  = blockIdx.x * 256 + threadIdx.x;      // 512 blocks x 256
    int sd = i & (SS*DD - 1);
    slots[i] = mu[sd] + sigma[sd] * noise[i];
}

// -------- row LayerNorm over D=256, one block per row --------
__global__ void ln_kernel(const float* __restrict__ in, float* __restrict__ out,
                          const float* __restrict__ g, const float* __restrict__ b){
    int row = blockIdx.x, t = threadIdx.x;
    int w = t >> 5, l = t & 31;
    float x = in[row*DD + t];
    __shared__ float s1[8], s2[8];
    float ps = warpSum(x);
    if (l == 0) s1[w] = ps;
    __syncthreads();
    if (w == 0){
        float v = (l < 8) ? s1[l] : 0.f;
        v = warpSum(v);
        if (l == 0) s1[0] = v * (1.f/256.f);
    }
    __syncthreads();
    float mean = s1[0];
    float d = x - mean;
    float pv = warpSum(d*d);
    if (l == 0) s2[w] = pv;
    __syncthreads();
    if (w == 0){
        float v = (l < 8) ? s2[l] : 0.f;
        v = warpSum(v);
        if (l == 0) s2[0] = rsqrtf(v * (1.f/256.f) + 1e-5f);
    }
    __syncthreads();
    out[row*DD + t] = d * s2[0] * g[t] + b[t];
}

// -------- generic small GEMM: C[M,N] = act(scale*A@B(^T) + bias) (+resid) --------
// BM=32, BN=64, BK=16, 128 threads, 4x4 per thread. A may be a sum of aSlices slices.
template<bool TRANSB>
__global__ void gemm_kernel(const float* __restrict__ A, const float* __restrict__ Bm,
                            const float* __restrict__ bias, const float* __restrict__ resid,
                            float* __restrict__ C,
                            int M, int Nn, int K, float scale, int doRelu,
                            int aSlices, int aStride)
{
    __shared__ float As[16*36];
    __shared__ float Bs[16*68];
    int tid = threadIdx.x;
    int tx = tid & 15, ty = tid >> 4;
    int m0 = blockIdx.y * 32, n0 = blockIdx.x * 64;
    float acc[4][4] = {};

    for (int k0 = 0; k0 < K; k0 += 16){
#pragma unroll
        for (int p = 0; p < 4; ++p){
            int idx = tid + p*128;
            int kk = idx & 15, mm = idx >> 4;
            const float* ap = A + (size_t)(m0+mm)*K + k0 + kk;
            float v = 0.f;
            for (int c = 0; c < aSlices; ++c) v += ap[(size_t)c * aStride];
            As[kk*36 + mm] = v;
        }
        if (TRANSB){
#pragma unroll
            for (int p = 0; p < 8; ++p){
                int idx = tid + p*128;
                int kk = idx & 15, nn = idx >> 4;
                Bs[kk*68 + nn] = Bm[(size_t)(n0+nn)*K + k0 + kk];
            }
        } else {
#pragma unroll
            for (int p = 0; p < 8; ++p){
                int idx = tid + p*128;
                int nn = idx & 63, kk = idx >> 6;
                Bs[kk*68 + nn] = Bm[(size_t)(k0+kk)*Nn + n0 + nn];
            }
        }
        __syncthreads();
#pragma unroll
        for (int k = 0; k < 16; ++k){
            float4 a4 = *(const float4*)&As[k*36 + ty*4];
            float4 b4 = *(const float4*)&Bs[k*68 + tx*4];
            float av[4] = {a4.x, a4.y, a4.z, a4.w};
            float bv[4] = {b4.x, b4.y, b4.z, b4.w};
#pragma unroll
            for (int i = 0; i < 4; ++i)
#pragma unroll
                for (int j = 0; j < 4; ++j) acc[i][j] += av[i]*bv[j];
        }
        __syncthreads();
    }
#pragma unroll
    for (int i = 0; i < 4; ++i){
        int row = m0 + ty*4 + i;
#pragma unroll
        for (int j = 0; j < 4; ++j){
            int col = n0 + tx*4 + j;
            float v = acc[i][j] * scale;
            if (bias)   v += bias[col];
            if (doRelu) v = fmaxf(v, 0.f);
            if (resid)  v += resid[(size_t)row*Nn + col];
            C[(size_t)row*Nn + col] = v;
        }
    }
}

// -------- logits[b,s,n] = qW[b,s,:] . inputs[b,n,:]  (qW pre-scaled by 1/sqrt(D)) -----
// grid (B, NCHUNK), 256 threads; each thread owns 2 n's x 8 s accumulators.
__global__ void logits_kernel(const float* __restrict__ qW,
                              const float* __restrict__ inputs,
                              float* __restrict__ logits){
    int b = blockIdx.x, ch = blockIdx.y;
    int t = threadIdx.x;
    __shared__ float qs[SS*IND];       // 8 KB
    __shared__ float ins[NT*17];       // 34 KB, stride-17: conflict-free
#pragma unroll
    for (int p = 0; p < 8; ++p){
        int idx = t + p*256;
        qs[idx] = qW[(size_t)b*(SS*IND) + idx];
    }
    float acc0[8] = {}, acc1[8] = {};
    const size_t base = ((size_t)b*NN + (size_t)ch*NT) * IND;

    for (int kc = 0; kc < IND; kc += 16){
        __syncthreads();
#pragma unroll
        for (int p = 0; p < 32; ++p){
            int idx = t + p*256;
            int kk = idx & 15, n = idx >> 4;
            ins[n*17 + kk] = inputs[base + (size_t)n*IND + kc + kk];
        }
        __syncthreads();
#pragma unroll
        for (int kk = 0; kk < 16; ++kk){
            float x0 = ins[t*17 + kk];
            float x1 = ins[(t+256)*17 + kk];
#pragma unroll
            for (int s = 0; s < 8; ++s){
                float qv = qs[s*IND + kc + kk];
                acc0[s] += x0 * qv;
                acc1[s] += x1 * qv;
            }
        }
    }
#pragma unroll
    for (int s = 0; s < 8; ++s){
        size_t o = ((size_t)(b*SS + s))*NN + (size_t)ch*NT;
        logits[o + t]       = acc0[s];
        logits[o + t + 256] = acc1[s];
    }
}

// -------- row softmax over N=4096, one block per (b,s) row --------
__global__ void softmax_kernel(float* __restrict__ a){
    int row = blockIdx.x, t = threadIdx.x;
    int w = t >> 5, l = t & 31;
    float4* p = (float4*)(a + (size_t)row*NN);
    float4 v[4];
#pragma unroll
    for (int i = 0; i < 4; ++i) v[i] = p[t + i*256];
    float m = -3.4e38f;
#pragma unroll
    for (int i = 0; i < 4; ++i){
        m = fmaxf(m, fmaxf(fmaxf(v[i].x, v[i].y), fmaxf(v[i].z, v[i].w)));
    }
    __shared__ float sm[8], ss[8];
    m = warpMax(m);
    if (l == 0) sm[w] = m;
    __syncthreads();
    if (w == 0){
        float x = (l < 8) ? sm[l] : -3.4e38f;
        x = warpMax(x);
        if (l == 0) sm[0] = x;
    }
    __syncthreads();
    m = sm[0];
    float sum = 0.f;
#pragma unroll
    for (int i = 0; i < 4; ++i){
        v[i].x = __expf(v[i].x - m); v[i].y = __expf(v[i].y - m);
        v[i].z = __expf(v[i].z - m); v[i].w = __expf(v[i].w - m);
        sum += v[i].x + v[i].y + v[i].z + v[i].w;
    }
    sum = warpSum(sum);
    if (l == 0) ss[w] = sum;
    __syncthreads();
    if (w == 0){
        float x = (l < 8) ? ss[l] : 0.f;
        x = warpSum(x);
        if (l == 0) ss[0] = 1.f / x;
    }
    __syncthreads();
    float inv = ss[0];
#pragma unroll
    for (int i = 0; i < 4; ++i){
        v[i].x *= inv; v[i].y *= inv; v[i].z *= inv; v[i].w *= inv;
        p[t + i*256] = v[i];
    }
}

// -------- U partials: upart[ch,b,s,e] = sum_{n in chunk} attn[b,s,n]*inputs[b,n,e] ----
__global__ void u_kernel(const float* __restrict__ attn,
                         const float* __restrict__ inputs,
                         float* __restrict__ upart){
    int b = blockIdx.x, ch = blockIdx.y;
    int t = threadIdx.x;
    __shared__ float at[SS*NT];    // 16 KB
#pragma unroll
    for (int p = 0; p < 16; ++p){
        int idx = t + p*256;
        int s = idx >> 9, n = idx & (NT-1);
        at[idx] = attn[((size_t)(b*SS + s))*NN + (size_t)ch*NT + n];
    }
    __syncthreads();
    float acc[8] = {};
    const float* ip = inputs + ((size_t)b*NN + (size_t)ch*NT)*IND + t;
#pragma unroll 4
    for (int n = 0; n < NT; ++n){
        float x = __ldg(ip + (size_t)n*IND);
#pragma unroll
        for (int s = 0; s < 8; ++s) acc[s] += at[s*NT + n] * x;
    }
#pragma unroll
    for (int s = 0; s < 8; ++s)
        upart[(((size_t)ch*BB + b)*SS + s)*IND + t] = acc[s];
}

// -------- GRU cell + residual, in-place on slots --------
__global__ void gru_kernel(const float* __restrict__ gi, const float* __restrict__ gh,
                           float* __restrict__ slots){
    int row = blockIdx.x, t = threadIdx.x;
    size_t g = (size_t)row*(3*DD) + t;
    float ir = gi[g], iz = gi[g+DD], in_ = gi[g+2*DD];
    float hr = gh[g], hz = gh[g+DD], hn  = gh[g+2*DD];
    float r = 1.f / (1.f + expf(-(ir + hr)));
    float z = 1.f / (1.f + expf(-(iz + hz)));
    float n = tanhf(in_ + r*hn);
    size_t si = (size_t)row*DD + t;
    float h = slots[si];
    slots[si] = h + (1.f - z)*n + z*h;   // slots_prev + h_new
}

// ------------------------- host launcher -------------------------
extern "C" void kernel_launch(void* const* d_in, const int* in_sizes, int n_in,
                              void* d_out, int out_size)
{
    const float* inputs = (const float*)d_in[0];
    const float* noise  = (const float*)d_in[1];
    const float* s_mu   = (const float*)d_in[2];
    const float* s_sig  = (const float*)d_in[3];
    const float* Wq = (const float*)d_in[4];  const float* bq = (const float*)d_in[5];
    const float* Wk = (const float*)d_in[6];  /* bk = d_in[7] : provably dead (softmax shift) */
    const float* Wv = (const float*)d_in[8];  const float* bv = (const float*)d_in[9];
    const float* W_ih = (const float*)d_in[10]; const float* b_ih = (const float*)d_in[11];
    const float* W_hh = (const float*)d_in[12]; const float* b_hh = (const float*)d_in[13];
    const float* W1 = (const float*)d_in[14]; const float* b1 = (const float*)d_in[15];
    const float* W2 = (const float*)d_in[16]; const float* b2 = (const float*)d_in[17];
    const float* lnsg = (const float*)d_in[18]; const float* lnsb = (const float*)d_in[19];
    const float* lnmg = (const float*)d_in[20]; const float* lnmb = (const float*)d_in[21];
    float* out = (float*)d_out;
    (void)in_sizes; (void)n_in; (void)out_size;

    float *slots, *ln, *q, *qW, *attn, *upart, *upd, *gi, *gh, *hidden;
    cudaGetSymbolAddress((void**)&slots,  g_slots);
    cudaGetSymbolAddress((void**)&ln,     g_ln);
    cudaGetSymbolAddress((void**)&q,      g_q);
    cudaGetSymbolAddress((void**)&qW,     g_qW);
    cudaGetSymbolAddress((void**)&attn,   g_attn);
    cudaGetSymbolAddress((void**)&upart,  g_upart);
    cudaGetSymbolAddress((void**)&upd,    g_upd);
    cudaGetSymbolAddress((void**)&gi,     g_gi);
    cudaGetSymbolAddress((void**)&gh,     g_gh);
    cudaGetSymbolAddress((void**)&hidden, g_hidden);

    const float inv_sqrt_d = 0.0625f;           // 1/sqrt(256)
    dim3 g256(256/64, ROWS/32);                 // (4,16)
    dim3 g768(768/64, ROWS/32);                 // (12,16)
    dim3 gBN(BB, NCHUNK);

    init_slots_kernel<<<ROWS, 256>>>(noise, s_mu, s_sig, slots);

    for (int it = 0; it < 3; ++it){
        // q = LN(slots) @ Wq^T + bq ; qW = (q @ Wk) * inv_sqrt_d  (bk folded out)
        ln_kernel<<<ROWS, 256>>>(slots, ln, lnsg, lnsb);
        gemm_kernel<true ><<<g256, 128>>>(ln, Wq, bq, nullptr, q,  ROWS, 256, 256, 1.f, 0, 1, 0);
        gemm_kernel<false><<<g256, 128>>>(q,  Wk, nullptr, nullptr, qW, ROWS, 256, 256, inv_sqrt_d, 0, 1, 0);

        // attention over inputs directly (k never materialized)
        logits_kernel<<<gBN, 256>>>(qW, inputs, attn);
        softmax_kernel<<<ROWS, 256>>>(attn);
        u_kernel<<<gBN, 256>>>(attn, inputs, upart);

        // updates = (sum_ch upart) @ Wv^T + bv   (sum(attn)=1 folds bv)
        gemm_kernel<true><<<g256, 128>>>(upart, Wv, bv, nullptr, upd,
                                         ROWS, 256, 256, 1.f, 0, NCHUNK, BB*SS*IND);

        // GRU
        gemm_kernel<true><<<g768, 128>>>(upd,   W_ih, b_ih, nullptr, gi, ROWS, 768, 256, 1.f, 0, 1, 0);
        gemm_kernel<true><<<g768, 128>>>(slots, W_hh, b_hh, nullptr, gh, ROWS, 768, 256, 1.f, 0, 1, 0);
        gru_kernel<<<ROWS, 256>>>(gi, gh, slots);

        // MLP residual
        ln_kernel<<<ROWS, 256>>>(slots, ln, lnmg, lnmb);
        gemm_kernel<true><<<g256, 128>>>(ln, W1, b1, nullptr, hidden, ROWS, 256, 256, 1.f, 1, 1, 0);
        float* cdst = (it == 2) ? out : slots;
        gemm_kernel<true><<<g256, 128>>>(hidden, W2, b2, slots, cdst, ROWS, 256, 256, 1.f, 0, 1, 0);
    }
}

// round 4
// speedup vs baseline: 1.3013x; 1.3013x over previous
#include <cuda_runtime.h>
#include <math.h>

// Problem constants
#define BB   64
#define NN   4096
#define IND  256
#define SS   8
#define DD   256
#define ROWS (BB*SS)        // 512
#define NCHUNK 8
#define NT   (NN/NCHUNK)    // 512 n's per chunk

// -------- scratch (device globals; no allocation allowed) --------
__device__ float g_slots [ROWS*DD];
__device__ float g_qW    [ROWS*IND];
__device__ float g_attn  [BB*SS*NN];          // logits then attn in-place (8 MB)
__device__ float g_upart [NCHUNK*BB*SS*IND];  // 4 MB partials of attn@X

// -------- reductions --------
__device__ __forceinline__ float warpSum(float v){
#pragma unroll
    for (int o = 16; o > 0; o >>= 1) v += __shfl_xor_sync(0xffffffffu, v, o);
    return v;
}
__device__ __forceinline__ float warpMax(float v){
#pragma unroll
    for (int o = 16; o > 0; o >>= 1) v = fmaxf(v, __shfl_xor_sync(0xffffffffu, v, o));
    return v;
}

// Block LayerNorm of 4 rows held column-wise in registers: thread t holds v[r] = X[r][t].
// Produces o[r] = (v-mean)*rstd*g[t] + b[t]. 256 threads.
__device__ __forceinline__ void block_ln4(const float v[4], float o[4],
                                          const float* __restrict__ g,
                                          const float* __restrict__ b, int t)
{
    __shared__ float part[8][4];
    __shared__ float stat[4];
    int w = t >> 5, l = t & 31;
#pragma unroll
    for (int r = 0; r < 4; ++r){
        float p = warpSum(v[r]);
        if (l == 0) part[w][r] = p;
    }
    __syncthreads();
    if (t < 32){
        int rr = l >> 3, ww = l & 7;
        float x = part[ww][rr];
        x += __shfl_xor_sync(0xffffffffu, x, 1);
        x += __shfl_xor_sync(0xffffffffu, x, 2);
        x += __shfl_xor_sync(0xffffffffu, x, 4);
        if (ww == 0) stat[rr] = x * (1.f/256.f);
    }
    __syncthreads();
    float d[4];
#pragma unroll
    for (int r = 0; r < 4; ++r) d[r] = v[r] - stat[r];
    __syncthreads();   // everyone done reading mean before stat reuse
#pragma unroll
    for (int r = 0; r < 4; ++r){
        float p = warpSum(d[r]*d[r]);
        if (l == 0) part[w][r] = p;
    }
    __syncthreads();
    if (t < 32){
        int rr = l >> 3, ww = l & 7;
        float x = part[ww][rr];
        x += __shfl_xor_sync(0xffffffffu, x, 1);
        x += __shfl_xor_sync(0xffffffffu, x, 2);
        x += __shfl_xor_sync(0xffffffffu, x, 4);
        if (ww == 0) stat[rr] = rsqrtf(x * (1.f/256.f) + 1e-5f);
    }
    __syncthreads();
    float gg = g[t], bb = b[t];
#pragma unroll
    for (int r = 0; r < 4; ++r) o[r] = d[r] * stat[r] * gg + bb;
}

// -------- slots = mu + sigma * noise --------
__global__ void init_slots_kernel(const float* __restrict__ noise,
                                  const float* __restrict__ mu,
                                  const float* __restrict__ sigma,
                                  float* __restrict__ slots){
    int i  = blockIdx.x * 256 + threadIdx.x;
    int sd = i & (SS*DD - 1);
    slots[i] = mu[sd] + sigma[sd] * noise[i];
}

// ============ PRE: LN(slots) -> q=ln@Wq^T+bq -> qW=(q@Wk)*inv_sqrt_d ============
// 128 blocks x 256 threads, 4 rows per block.
__global__ __launch_bounds__(256) void pre_kernel(
        const float* __restrict__ slots,
        const float* __restrict__ lng, const float* __restrict__ lnb,
        const float* __restrict__ Wq,  const float* __restrict__ bq,
        const float* __restrict__ Wk,
        float* __restrict__ qW)
{
    int r0 = blockIdx.x * 4;
    int t  = threadIdx.x;
    __shared__ float s_ln[4][DD];
    __shared__ float s_q [4][DD];

    float v[4];
#pragma unroll
    for (int r = 0; r < 4; ++r) v[r] = slots[(size_t)(r0+r)*DD + t];
    float o[4];
    block_ln4(v, o, lng, lnb, t);
#pragma unroll
    for (int r = 0; r < 4; ++r) s_ln[r][t] = o[r];
    __syncthreads();

    // q[r, n=t] = sum_k s_ln[r][k] * Wq[t][k] + bq[t]
    {
        const float4* wrow = reinterpret_cast<const float4*>(Wq + (size_t)t*DD);
        float a0=0.f, a1=0.f, a2=0.f, a3=0.f;
#pragma unroll 8
        for (int k4 = 0; k4 < 64; ++k4){
            float4 wv = __ldg(&wrow[k4]);
            int k = k4*4;
            a0 += s_ln[0][k]*wv.x + s_ln[0][k+1]*wv.y + s_ln[0][k+2]*wv.z + s_ln[0][k+3]*wv.w;
            a1 += s_ln[1][k]*wv.x + s_ln[1][k+1]*wv.y + s_ln[1][k+2]*wv.z + s_ln[1][k+3]*wv.w;
            a2 += s_ln[2][k]*wv.x + s_ln[2][k+1]*wv.y + s_ln[2][k+2]*wv.z + s_ln[2][k+3]*wv.w;
            a3 += s_ln[3][k]*wv.x + s_ln[3][k+1]*wv.y + s_ln[3][k+2]*wv.z + s_ln[3][k+3]*wv.w;
        }
        float bv = __ldg(&bq[t]);
        s_q[0][t] = a0 + bv; s_q[1][t] = a1 + bv;
        s_q[2][t] = a2 + bv; s_q[3][t] = a3 + bv;
    }
    __syncthreads();

    // qW[r, e=t] = (sum_d s_q[r][d] * Wk[d][t]) / 16   (coalesced column stream)
    {
        float c0=0.f, c1=0.f, c2=0.f, c3=0.f;
#pragma unroll 8
        for (int d = 0; d < DD; ++d){
            float wv = __ldg(&Wk[(size_t)d*IND + t]);
            c0 += s_q[0][d]*wv; c1 += s_q[1][d]*wv;
            c2 += s_q[2][d]*wv; c3 += s_q[3][d]*wv;
        }
        qW[(size_t)(r0+0)*IND + t] = c0 * 0.0625f;
        qW[(size_t)(r0+1)*IND + t] = c1 * 0.0625f;
        qW[(size_t)(r0+2)*IND + t] = c2 * 0.0625f;
        qW[(size_t)(r0+3)*IND + t] = c3 * 0.0625f;
    }
}

// ============ logits[b,s,n] = qW[b,s,:] . inputs[b,n,:] ============
__global__ void logits_kernel(const float* __restrict__ qW,
                              const float* __restrict__ inputs,
                              float* __restrict__ logits){
    int b = blockIdx.x, ch = blockIdx.y;
    int t = threadIdx.x;
    __shared__ float qs[SS*IND];
    __shared__ float ins[NT*17];
#pragma unroll
    for (int p = 0; p < 8; ++p){
        int idx = t + p*256;
        qs[idx] = qW[(size_t)b*(SS*IND) + idx];
    }
    float acc0[8] = {}, acc1[8] = {};
    const size_t base = ((size_t)b*NN + (size_t)ch*NT) * IND;

    for (int kc = 0; kc < IND; kc += 16){
        __syncthreads();
#pragma unroll
        for (int p = 0; p < 32; ++p){
            int idx = t + p*256;
            int kk = idx & 15, n = idx >> 4;
            ins[n*17 + kk] = inputs[base + (size_t)n*IND + kc + kk];
        }
        __syncthreads();
#pragma unroll
        for (int kk = 0; kk < 16; ++kk){
            float x0 = ins[t*17 + kk];
            float x1 = ins[(t+256)*17 + kk];
#pragma unroll
            for (int s = 0; s < 8; ++s){
                float qv = qs[s*IND + kc + kk];
                acc0[s] += x0 * qv;
                acc1[s] += x1 * qv;
            }
        }
    }
#pragma unroll
    for (int s = 0; s < 8; ++s){
        size_t o = ((size_t)(b*SS + s))*NN + (size_t)ch*NT;
        logits[o + t]       = acc0[s];
        logits[o + t + 256] = acc1[s];
    }
}

// ============ row softmax over N=4096 ============
__global__ void softmax_kernel(float* __restrict__ a){
    int row = blockIdx.x, t = threadIdx.x;
    int w = t >> 5, l = t & 31;
    float4* p = (float4*)(a + (size_t)row*NN);
    float4 v[4];
#pragma unroll
    for (int i = 0; i < 4; ++i) v[i] = p[t + i*256];
    float m = -3.4e38f;
#pragma unroll
    for (int i = 0; i < 4; ++i)
        m = fmaxf(m, fmaxf(fmaxf(v[i].x, v[i].y), fmaxf(v[i].z, v[i].w)));
    __shared__ float sm[8], ss[8];
    m = warpMax(m);
    if (l == 0) sm[w] = m;
    __syncthreads();
    if (w == 0){
        float x = (l < 8) ? sm[l] : -3.4e38f;
        x = warpMax(x);
        if (l == 0) sm[0] = x;
    }
    __syncthreads();
    m = sm[0];
    float sum = 0.f;
#pragma unroll
    for (int i = 0; i < 4; ++i){
        v[i].x = __expf(v[i].x - m); v[i].y = __expf(v[i].y - m);
        v[i].z = __expf(v[i].z - m); v[i].w = __expf(v[i].w - m);
        sum += v[i].x + v[i].y + v[i].z + v[i].w;
    }
    sum = warpSum(sum);
    if (l == 0) ss[w] = sum;
    __syncthreads();
    if (w == 0){
        float x = (l < 8) ? ss[l] : 0.f;
        x = warpSum(x);
        if (l == 0) ss[0] = 1.f / x;
    }
    __syncthreads();
    float inv = ss[0];
#pragma unroll
    for (int i = 0; i < 4; ++i){
        v[i].x *= inv; v[i].y *= inv; v[i].z *= inv; v[i].w *= inv;
        p[t + i*256] = v[i];
    }
}

// ============ U partials: upart[ch, row, e] = sum_{n in chunk} attn*inputs ============
__global__ void u_kernel(const float* __restrict__ attn,
                         const float* __restrict__ inputs,
                         float* __restrict__ upart){
    int b = blockIdx.x, ch = blockIdx.y;
    int t = threadIdx.x;
    __shared__ float at[SS*NT];
#pragma unroll
    for (int p = 0; p < 16; ++p){
        int idx = t + p*256;
        int s = idx >> 9, n = idx & (NT-1);
        at[idx] = attn[((size_t)(b*SS + s))*NN + (size_t)ch*NT + n];
    }
    __syncthreads();
    float acc[8] = {};
    const float* ip = inputs + ((size_t)b*NN + (size_t)ch*NT)*IND + t;
#pragma unroll 2
    for (int n4 = 0; n4 < NT; n4 += 4){
        float x0 = __ldg(ip + (size_t)(n4+0)*IND);
        float x1 = __ldg(ip + (size_t)(n4+1)*IND);
        float x2 = __ldg(ip + (size_t)(n4+2)*IND);
        float x3 = __ldg(ip + (size_t)(n4+3)*IND);
#pragma unroll
        for (int s = 0; s < 8; ++s){
            float4 w = *(const float4*)&at[s*NT + n4];
            acc[s] += w.x*x0 + w.y*x1 + w.z*x2 + w.w*x3;
        }
    }
#pragma unroll
    for (int s = 0; s < 8; ++s)
        upart[(((size_t)ch*BB + b)*SS + s)*IND + t] = acc[s];
}

// ============ POST: sum(upart)->Wv^T+bv -> GRU(gi,gh)+resid -> LN -> MLP+resid ======
// 128 blocks x 256 threads, 4 rows per block. One launch replaces 8 kernels.
__global__ __launch_bounds__(256) void post_kernel(
        const float* __restrict__ upart,
        const float* __restrict__ Wv,   const float* __restrict__ bv,
        const float* __restrict__ W_ih, const float* __restrict__ b_ih,
        const float* __restrict__ W_hh, const float* __restrict__ b_hh,
        const float* __restrict__ lng,  const float* __restrict__ lnb,
        const float* __restrict__ W1,   const float* __restrict__ b1,
        const float* __restrict__ W2,   const float* __restrict__ b2,
        const float* __restrict__ slots_in,
        float* __restrict__ dst)
{
    int r0 = blockIdx.x * 4;
    int t  = threadIdx.x;
    __shared__ float sU   [4][DD];
    __shared__ float sprev[4][DD];
    __shared__ float supd [4][DD];
    __shared__ float sgi  [4][3*DD];
    __shared__ float sgh  [4][3*DD];
    __shared__ float sln  [4][DD];
    __shared__ float shid [4][DD];

    // 1. U = sum of 8 chunk partials; load slots_prev
#pragma unroll
    for (int r = 0; r < 4; ++r){
        float a = 0.f;
#pragma unroll
        for (int ch = 0; ch < NCHUNK; ++ch)
            a += upart[((size_t)ch*ROWS + (r0+r))*IND + t];
        sU[r][t]    = a;
        sprev[r][t] = slots_in[(size_t)(r0+r)*DD + t];
    }
    __syncthreads();

    // 2. upd[r, n=t] = sum_e U[r][e] * Wv[t][e] + bv[t]
    {
        const float4* wrow = reinterpret_cast<const float4*>(Wv + (size_t)t*IND);
        float a0=0.f,a1=0.f,a2=0.f,a3=0.f;
#pragma unroll 8
        for (int k4 = 0; k4 < 64; ++k4){
            float4 wv = __ldg(&wrow[k4]);
            int k = 4*k4;
            a0 += sU[0][k]*wv.x + sU[0][k+1]*wv.y + sU[0][k+2]*wv.z + sU[0][k+3]*wv.w;
            a1 += sU[1][k]*wv.x + sU[1][k+1]*wv.y + sU[1][k+2]*wv.z + sU[1][k+3]*wv.w;
            a2 += sU[2][k]*wv.x + sU[2][k+1]*wv.y + sU[2][k+2]*wv.z + sU[2][k+3]*wv.w;
            a3 += sU[3][k]*wv.x + sU[3][k+1]*wv.y + sU[3][k+2]*wv.z + sU[3][k+3]*wv.w;
        }
        float bb = __ldg(&bv[t]);
        supd[0][t] = a0 + bb; supd[1][t] = a1 + bb;
        supd[2][t] = a2 + bb; supd[3][t] = a3 + bb;
    }
    __syncthreads();

    // 3. gi = upd @ W_ih^T + b_ih   (3 output cols per thread: t, t+256, t+512)
    {
        float acc[3][4] = {};
        const float4* w0 = reinterpret_cast<const float4*>(W_ih + (size_t)(t      )*DD);
        const float4* w1 = reinterpret_cast<const float4*>(W_ih + (size_t)(t + 256)*DD);
        const float4* w2 = reinterpret_cast<const float4*>(W_ih + (size_t)(t + 512)*DD);
#pragma unroll 4
        for (int k4 = 0; k4 < 64; ++k4){
            float4 a0 = __ldg(&w0[k4]);
            float4 a1 = __ldg(&w1[k4]);
            float4 a2 = __ldg(&w2[k4]);
            int k = 4*k4;
#pragma unroll
            for (int r = 0; r < 4; ++r){
                float u0 = supd[r][k], u1 = supd[r][k+1], u2 = supd[r][k+2], u3 = supd[r][k+3];
                acc[0][r] += u0*a0.x + u1*a0.y + u2*a0.z + u3*a0.w;
                acc[1][r] += u0*a1.x + u1*a1.y + u2*a1.z + u3*a1.w;
                acc[2][r] += u0*a2.x + u1*a2.y + u2*a2.z + u3*a2.w;
            }
        }
#pragma unroll
        for (int j = 0; j < 3; ++j){
            float bb = __ldg(&b_ih[t + j*256]);
#pragma unroll
            for (int r = 0; r < 4; ++r) sgi[r][t + j*256] = acc[j][r] + bb;
        }
    }

    // 4. gh = slots_prev @ W_hh^T + b_hh
    {
        float acc[3][4] = {};
        const float4* w0 = reinterpret_cast<const float4*>(W_hh + (size_t)(t      )*DD);
        const float4* w1 = reinterpret_cast<const float4*>(W_hh + (size_t)(t + 256)*DD);
        const float4* w2 = reinterpret_cast<const float4*>(W_hh + (size_t)(t + 512)*DD);
#pragma unroll 4
        for (int k4 = 0; k4 < 64; ++k4){
            float4 a0 = __ldg(&w0[k4]);
            float4 a1 = __ldg(&w1[k4]);
            float4 a2 = __ldg(&w2[k4]);
            int k = 4*k4;
#pragma unroll
            for (int r = 0; r < 4; ++r){
                float u0 = sprev[r][k], u1 = sprev[r][k+1], u2 = sprev[r][k+2], u3 = sprev[r][k+3];
                acc[0][r] += u0*a0.x + u1*a0.y + u2*a0.z + u3*a0.w;
                acc[1][r] += u0*a1.x + u1*a1.y + u2*a1.z + u3*a1.w;
                acc[2][r] += u0*a2.x + u1*a2.y + u2*a2.z + u3*a2.w;
            }
        }
#pragma unroll
        for (int j = 0; j < 3; ++j){
            float bb = __ldg(&b_hh[t + j*256]);
#pragma unroll
            for (int r = 0; r < 4; ++r) sgh[r][t + j*256] = acc[j][r] + bb;
        }
    }
    __syncthreads();

    // 5. GRU cell + residual (register result vnew[r])
    float vnew[4];
#pragma unroll
    for (int r = 0; r < 4; ++r){
        float ir = sgi[r][t], iz = sgi[r][t+256], inn = sgi[r][t+512];
        float hr = sgh[r][t], hz = sgh[r][t+256], hn  = sgh[r][t+512];
        float rr = 1.f / (1.f + expf(-(ir + hr)));
        float zz = 1.f / (1.f + expf(-(iz + hz)));
        float nn = tanhf(inn + rr*hn);
        float h  = sprev[r][t];
        vnew[r]  = h + (1.f - zz)*nn + zz*h;
    }

    // 6. LN(vnew)
    float lnv[4];
    block_ln4(vnew, lnv, lng, lnb, t);
#pragma unroll
    for (int r = 0; r < 4; ++r) sln[r][t] = lnv[r];
    __syncthreads();

    // 7. hidden = relu(sln @ W1^T + b1)
    {
        const float4* wrow = reinterpret_cast<const float4*>(W1 + (size_t)t*DD);
        float a0=0.f,a1=0.f,a2=0.f,a3=0.f;
#pragma unroll 8
        for (int k4 = 0; k4 < 64; ++k4){
            float4 wv = __ldg(&wrow[k4]);
            int k = 4*k4;
            a0 += sln[0][k]*wv.x + sln[0][k+1]*wv.y + sln[0][k+2]*wv.z + sln[0][k+3]*wv.w;
            a1 += sln[1][k]*wv.x + sln[1][k+1]*wv.y + sln[1][k+2]*wv.z + sln[1][k+3]*wv.w;
            a2 += sln[2][k]*wv.x + sln[2][k+1]*wv.y + sln[2][k+2]*wv.z + sln[2][k+3]*wv.w;
            a3 += sln[3][k]*wv.x + sln[3][k+1]*wv.y + sln[3][k+2]*wv.z + sln[3][k+3]*wv.w;
        }
        float bb = __ldg(&b1[t]);
        shid[0][t] = fmaxf(a0 + bb, 0.f);
        shid[1][t] = fmaxf(a1 + bb, 0.f);
        shid[2][t] = fmaxf(a2 + bb, 0.f);
        shid[3][t] = fmaxf(a3 + bb, 0.f);
    }
    __syncthreads();

    // 8. out = vnew + hidden @ W2^T + b2
    {
        const float4* wrow = reinterpret_cast<const float4*>(W2 + (size_t)t*DD);
        float a0=0.f,a1=0.f,a2=0.f,a3=0.f;
#pragma unroll 8
        for (int k4 = 0; k4 < 64; ++k4){
            float4 wv = __ldg(&wrow[k4]);
            int k = 4*k4;
            a0 += shid[0][k]*wv.x + shid[0][k+1]*wv.y + shid[0][k+2]*wv.z + shid[0][k+3]*wv.w;
            a1 += shid[1][k]*wv.x + shid[1][k+1]*wv.y + shid[1][k+2]*wv.z + shid[1][k+3]*wv.w;
            a2 += shid[2][k]*wv.x + shid[2][k+1]*wv.y + shid[2][k+2]*wv.z + shid[2][k+3]*wv.w;
            a3 += shid[3][k]*wv.x + shid[3][k+1]*wv.y + shid[3][k+2]*wv.z + shid[3][k+3]*wv.w;
        }
        float bb = __ldg(&b2[t]);
        dst[(size_t)(r0+0)*DD + t] = vnew[0] + a0 + bb;
        dst[(size_t)(r0+1)*DD + t] = vnew[1] + a1 + bb;
        dst[(size_t)(r0+2)*DD + t] = vnew[2] + a2 + bb;
        dst[(size_t)(r0+3)*DD + t] = vnew[3] + a3 + bb;
    }
}

// ------------------------- host launcher -------------------------
extern "C" void kernel_launch(void* const* d_in, const int* in_sizes, int n_in,
                              void* d_out, int out_size)
{
    const float* inputs = (const float*)d_in[0];
    const float* noise  = (const float*)d_in[1];
    const float* s_mu   = (const float*)d_in[2];
    const float* s_sig  = (const float*)d_in[3];
    const float* Wq = (const float*)d_in[4];  const float* bq = (const float*)d_in[5];
    const float* Wk = (const float*)d_in[6];  /* bk = d_in[7] : dead (softmax shift-invariance) */
    const float* Wv = (const float*)d_in[8];  const float* bv = (const float*)d_in[9];
    const float* W_ih = (const float*)d_in[10]; const float* b_ih = (const float*)d_in[11];
    const float* W_hh = (const float*)d_in[12]; const float* b_hh = (const float*)d_in[13];
    const float* W1 = (const float*)d_in[14]; const float* b1 = (const float*)d_in[15];
    const float* W2 = (const float*)d_in[16]; const float* b2 = (const float*)d_in[17];
    const float* lnsg = (const float*)d_in[18]; const float* lnsb = (const float*)d_in[19];
    const float* lnmg = (const float*)d_in[20]; const float* lnmb = (const float*)d_in[21];
    float* out = (float*)d_out;
    (void)in_sizes; (void)n_in; (void)out_size;

    float *slots, *qW, *attn, *upart;
    cudaGetSymbolAddress((void**)&slots, g_slots);
    cudaGetSymbolAddress((void**)&qW,    g_qW);
    cudaGetSymbolAddress((void**)&attn,  g_attn);
    cudaGetSymbolAddress((void**)&upart, g_upart);

    dim3 gBN(BB, NCHUNK);

    init_slots_kernel<<<ROWS, 256>>>(noise, s_mu, s_sig, slots);

    for (int it = 0; it < 3; ++it){
        pre_kernel<<<ROWS/4, 256>>>(slots, lnsg, lnsb, Wq, bq, Wk, qW);
        logits_kernel<<<gBN, 256>>>(qW, inputs, attn);
        softmax_kernel<<<ROWS, 256>>>(attn);
        u_kernel<<<gBN, 256>>>(attn, inputs, upart);
        float* dst = (it == 2) ? out : slots;
        post_kernel<<<ROWS/4, 256>>>(upart, Wv, bv, W_ih, b_ih, W_hh, b_hh,
                                     lnmg, lnmb, W1, b1, W2, b2, slots, dst);
    }
}

// round 5
// speedup vs baseline: 1.3391x; 1.0290x over previous
#include <cuda_runtime.h>
#include <math.h>

// Problem constants
#define BB   64
#define NN   4096
#define IND  256
#define SS   8
#define DD   256
#define ROWS (BB*SS)        // 512
#define NCHUNK 8
#define NT   (NN/NCHUNK)    // 512 n's per chunk

// -------- scratch (device globals; no allocation allowed) --------
__device__ float g_slots [ROWS*DD];
__device__ float g_qW    [ROWS*IND];
__device__ float g_upart [NCHUNK*ROWS*IND];   // unnormalized U partials (4 MB)
__device__ float g_m     [NCHUNK*ROWS];       // per-chunk running max
__device__ float g_l     [NCHUNK*ROWS];       // per-chunk exp-sum

// -------- reductions --------
__device__ __forceinline__ float warpSum(float v){
#pragma unroll
    for (int o = 16; o > 0; o >>= 1) v += __shfl_xor_sync(0xffffffffu, v, o);
    return v;
}
__device__ __forceinline__ float warpMax(float v){
#pragma unroll
    for (int o = 16; o > 0; o >>= 1) v = fmaxf(v, __shfl_xor_sync(0xffffffffu, v, o));
    return v;
}

// Block LayerNorm of 4 rows held column-wise in registers: thread t holds v[r] = X[r][t].
__device__ __forceinline__ void block_ln4(const float v[4], float o[4],
                                          const float* __restrict__ g,
                                          const float* __restrict__ b, int t)
{
    __shared__ float part[8][4];
    __shared__ float stat[4];
    int w = t >> 5, l = t & 31;
#pragma unroll
    for (int r = 0; r < 4; ++r){
        float p = warpSum(v[r]);
        if (l == 0) part[w][r] = p;
    }
    __syncthreads();
    if (t < 32){
        int rr = l >> 3, ww = l & 7;
        float x = part[ww][rr];
        x += __shfl_xor_sync(0xffffffffu, x, 1);
        x += __shfl_xor_sync(0xffffffffu, x, 2);
        x += __shfl_xor_sync(0xffffffffu, x, 4);
        if (ww == 0) stat[rr] = x * (1.f/256.f);
    }
    __syncthreads();
    float d[4];
#pragma unroll
    for (int r = 0; r < 4; ++r) d[r] = v[r] - stat[r];
    __syncthreads();
#pragma unroll
    for (int r = 0; r < 4; ++r){
        float p = warpSum(d[r]*d[r]);
        if (l == 0) part[w][r] = p;
    }
    __syncthreads();
    if (t < 32){
        int rr = l >> 3, ww = l & 7;
        float x = part[ww][rr];
        x += __shfl_xor_sync(0xffffffffu, x, 1);
        x += __shfl_xor_sync(0xffffffffu, x, 2);
        x += __shfl_xor_sync(0xffffffffu, x, 4);
        if (ww == 0) stat[rr] = rsqrtf(x * (1.f/256.f) + 1e-5f);
    }
    __syncthreads();
    float gg = g[t], bb = b[t];
#pragma unroll
    for (int r = 0; r < 4; ++r) o[r] = d[r] * stat[r] * gg + bb;
}

// -------- slots = mu + sigma * noise --------
__global__ void init_slots_kernel(const float* __restrict__ noise,
                                  const float* __restrict__ mu,
                                  const float* __restrict__ sigma,
                                  float* __restrict__ slots){
    int i  = blockIdx.x * 256 + threadIdx.x;
    int sd = i & (SS*DD - 1);
    slots[i] = mu[sd] + sigma[sd] * noise[i];
}

// ============ PRE: LN(slots) -> q=ln@Wq^T+bq -> qW=(q@Wk)*inv_sqrt_d ============
__global__ __launch_bounds__(256) void pre_kernel(
        const float* __restrict__ slots,
        const float* __restrict__ lng, const float* __restrict__ lnb,
        const float* __restrict__ Wq,  const float* __restrict__ bq,
        const float* __restrict__ Wk,
        float* __restrict__ qW)
{
    int r0 = blockIdx.x * 4;
    int t  = threadIdx.x;
    __shared__ float s_ln[4][DD];
    __shared__ float s_q [4][DD];

    float v[4];
#pragma unroll
    for (int r = 0; r < 4; ++r) v[r] = slots[(size_t)(r0+r)*DD + t];
    float o[4];
    block_ln4(v, o, lng, lnb, t);
#pragma unroll
    for (int r = 0; r < 4; ++r) s_ln[r][t] = o[r];
    __syncthreads();

    {   // q[r, n=t] = s_ln[r] . Wq[t,:] + bq[t]
        const float4* wrow = reinterpret_cast<const float4*>(Wq + (size_t)t*DD);
        float a0=0.f, a1=0.f, a2=0.f, a3=0.f;
#pragma unroll 8
        for (int k4 = 0; k4 < 64; ++k4){
            float4 wv = __ldg(&wrow[k4]);
            int k = k4*4;
            a0 += s_ln[0][k]*wv.x + s_ln[0][k+1]*wv.y + s_ln[0][k+2]*wv.z + s_ln[0][k+3]*wv.w;
            a1 += s_ln[1][k]*wv.x + s_ln[1][k+1]*wv.y + s_ln[1][k+2]*wv.z + s_ln[1][k+3]*wv.w;
            a2 += s_ln[2][k]*wv.x + s_ln[2][k+1]*wv.y + s_ln[2][k+2]*wv.z + s_ln[2][k+3]*wv.w;
            a3 += s_ln[3][k]*wv.x + s_ln[3][k+1]*wv.y + s_ln[3][k+2]*wv.z + s_ln[3][k+3]*wv.w;
        }
        float bv = __ldg(&bq[t]);
        s_q[0][t] = a0 + bv; s_q[1][t] = a1 + bv;
        s_q[2][t] = a2 + bv; s_q[3][t] = a3 + bv;
    }
    __syncthreads();

    {   // qW[r, e=t] = (s_q[r] @ Wk[:,t]) / 16
        float c0=0.f, c1=0.f, c2=0.f, c3=0.f;
#pragma unroll 8
        for (int d = 0; d < DD; ++d){
            float wv = __ldg(&Wk[(size_t)d*IND + t]);
            c0 += s_q[0][d]*wv; c1 += s_q[1][d]*wv;
            c2 += s_q[2][d]*wv; c3 += s_q[3][d]*wv;
        }
        qW[(size_t)(r0+0)*IND + t] = c0 * 0.0625f;
        qW[(size_t)(r0+1)*IND + t] = c1 * 0.0625f;
        qW[(size_t)(r0+2)*IND + t] = c2 * 0.0625f;
        qW[(size_t)(r0+3)*IND + t] = c3 * 0.0625f;
    }
}

// ============ FUSED attention: logits -> per-chunk softmax -> unnormalized U ========
// grid (B, NCHUNK), 256 threads. inputs tile (512KB) read from DRAM in phase 1,
// re-read from L2 (still hot) in phase 3.
__global__ __launch_bounds__(256) void attn_kernel(
        const float* __restrict__ qW,
        const float* __restrict__ inputs,
        float* __restrict__ upart,
        float* __restrict__ mbuf,
        float* __restrict__ lbuf)
{
    int b = blockIdx.x, ch = blockIdx.y;
    int t = threadIdx.x;
    int w = t >> 5, l = t & 31;
    __shared__ float qs[SS*IND];     // 8 KB
    __shared__ float ins[NT*17];     // 34 KB: 16-k slab of all 512 n, stride-17
    __shared__ float at[SS][NT];     // 16 KB: logits -> exp weights

    // ---- phase 1: logits (register-blocked: 2 n x 8 s per thread) ----
#pragma unroll
    for (int p = 0; p < 8; ++p){
        int idx = t + p*256;
        qs[idx] = qW[(size_t)b*(SS*IND) + idx];
    }
    float acc0[8] = {}, acc1[8] = {};
    const size_t base = ((size_t)b*NN + (size_t)ch*NT) * IND;

    for (int kc = 0; kc < IND; kc += 16){
        __syncthreads();
#pragma unroll
        for (int p = 0; p < 32; ++p){
            int idx = t + p*256;
            int kk = idx & 15, n = idx >> 4;
            ins[n*17 + kk] = inputs[base + (size_t)n*IND + kc + kk];
        }
        __syncthreads();
#pragma unroll
        for (int kk = 0; kk < 16; ++kk){
            float x0 = ins[t*17 + kk];
            float x1 = ins[(t+256)*17 + kk];
#pragma unroll
            for (int s = 0; s < 8; ++s){
                float qv = qs[s*IND + kc + kk];
                acc0[s] += x0 * qv;
                acc1[s] += x1 * qv;
            }
        }
    }
#pragma unroll
    for (int s = 0; s < 8; ++s){
        at[s][t]       = acc0[s];
        at[s][t + 256] = acc1[s];
    }
    __syncthreads();

    // ---- phase 2: per-chunk online softmax; warp w owns slot s=w ----
    {
        float mv = -3.4e38f;
#pragma unroll
        for (int i = 0; i < 16; ++i) mv = fmaxf(mv, at[w][l + i*32]);
        mv = warpMax(mv);
        float sum = 0.f;
#pragma unroll
        for (int i = 0; i < 16; ++i){
            float e = __expf(at[w][l + i*32] - mv);
            at[w][l + i*32] = e;
            sum += e;
        }
        sum = warpSum(sum);
        if (l == 0){
            int row = b*SS + w;
            mbuf[(size_t)ch*ROWS + row] = mv;
            lbuf[(size_t)ch*ROWS + row] = sum;
        }
    }
    __syncthreads();

    // ---- phase 3: Ubar[s][e=t] = sum_n at[s][n] * inputs[b, n0+n, e] (L2-hot) ----
    {
        float acc[8] = {};
        const float* ip = inputs + base + t;
#pragma unroll 2
        for (int n4 = 0; n4 < NT; n4 += 4){
            float x0 = __ldg(ip + (size_t)(n4+0)*IND);
            float x1 = __ldg(ip + (size_t)(n4+1)*IND);
            float x2 = __ldg(ip + (size_t)(n4+2)*IND);
            float x3 = __ldg(ip + (size_t)(n4+3)*IND);
#pragma unroll
            for (int s = 0; s < 8; ++s){
                float4 wv = *(const float4*)&at[s][n4];
                acc[s] += wv.x*x0 + wv.y*x1 + wv.z*x2 + wv.w*x3;
            }
        }
#pragma unroll
        for (int s = 0; s < 8; ++s)
            upart[((size_t)ch*ROWS + b*SS + s)*IND + t] = acc[s];
    }
}

// ============ POST: flash-combine -> Wv^T+bv -> GRU+resid -> LN -> MLP+resid ======
__global__ __launch_bounds__(256) void post_kernel(
        const float* __restrict__ upart,
        const float* __restrict__ mbuf, const float* __restrict__ lbuf,
        const float* __restrict__ Wv,   const float* __restrict__ bv,
        const float* __restrict__ W_ih, const float* __restrict__ b_ih,
        const float* __restrict__ W_hh, const float* __restrict__ b_hh,
        const float* __restrict__ lng,  const float* __restrict__ lnb,
        const float* __restrict__ W1,   const float* __restrict__ b1,
        const float* __restrict__ W2,   const float* __restrict__ b2,
        const float* __restrict__ slots_in,
        float* __restrict__ dst)
{
    int r0 = blockIdx.x * 4;
    int t  = threadIdx.x;
    __shared__ float sU   [4][DD];
    __shared__ float sprev[4][DD];
    __shared__ float supd [4][DD];
    __shared__ float sgi  [4][3*DD];
    __shared__ float sgh  [4][3*DD];
    __shared__ float sln  [4][DD];
    __shared__ float shid [4][DD];

    // 1. flash combine of 8 chunk partials: U = sum_ch Ubar_ch*e^{m_ch-m} / sum_ch l_ch*e^{m_ch-m}
#pragma unroll
    for (int r = 0; r < 4; ++r){
        int row = r0 + r;
        float mm = -3.4e38f;
#pragma unroll
        for (int ch = 0; ch < NCHUNK; ++ch)
            mm = fmaxf(mm, __ldg(&mbuf[(size_t)ch*ROWS + row]));
        float sc[NCHUNK];
        float lt = 0.f;
#pragma unroll
        for (int ch = 0; ch < NCHUNK; ++ch){
            sc[ch] = __expf(__ldg(&mbuf[(size_t)ch*ROWS + row]) - mm);
            lt += __ldg(&lbuf[(size_t)ch*ROWS + row]) * sc[ch];
        }
        float inv = 1.f / lt;
        float a = 0.f;
#pragma unroll
        for (int ch = 0; ch < NCHUNK; ++ch)
            a += upart[((size_t)ch*ROWS + row)*IND + t] * sc[ch];
        sU[r][t]    = a * inv;
        sprev[r][t] = slots_in[(size_t)row*DD + t];
    }
    __syncthreads();

    // 2. upd = U @ Wv^T + bv
    {
        const float4* wrow = reinterpret_cast<const float4*>(Wv + (size_t)t*IND);
        float a0=0.f,a1=0.f,a2=0.f,a3=0.f;
#pragma unroll 8
        for (int k4 = 0; k4 < 64; ++k4){
            float4 wv = __ldg(&wrow[k4]);
            int k = 4*k4;
            a0 += sU[0][k]*wv.x + sU[0][k+1]*wv.y + sU[0][k+2]*wv.z + sU[0][k+3]*wv.w;
            a1 += sU[1][k]*wv.x + sU[1][k+1]*wv.y + sU[1][k+2]*wv.z + sU[1][k+3]*wv.w;
            a2 += sU[2][k]*wv.x + sU[2][k+1]*wv.y + sU[2][k+2]*wv.z + sU[2][k+3]*wv.w;
            a3 += sU[3][k]*wv.x + sU[3][k+1]*wv.y + sU[3][k+2]*wv.z + sU[3][k+3]*wv.w;
        }
        float bb = __ldg(&bv[t]);
        supd[0][t] = a0 + bb; supd[1][t] = a1 + bb;
        supd[2][t] = a2 + bb; supd[3][t] = a3 + bb;
    }
    __syncthreads();

    // 3. gi = upd @ W_ih^T + b_ih
    {
        float acc[3][4] = {};
        const float4* w0 = reinterpret_cast<const float4*>(W_ih + (size_t)(t      )*DD);
        const float4* w1 = reinterpret_cast<const float4*>(W_ih + (size_t)(t + 256)*DD);
        const float4* w2 = reinterpret_cast<const float4*>(W_ih + (size_t)(t + 512)*DD);
#pragma unroll 4
        for (int k4 = 0; k4 < 64; ++k4){
            float4 a0 = __ldg(&w0[k4]);
            float4 a1 = __ldg(&w1[k4]);
            float4 a2 = __ldg(&w2[k4]);
            int k = 4*k4;
#pragma unroll
            for (int r = 0; r < 4; ++r){
                float u0 = supd[r][k], u1 = supd[r][k+1], u2 = supd[r][k+2], u3 = supd[r][k+3];
                acc[0][r] += u0*a0.x + u1*a0.y + u2*a0.z + u3*a0.w;
                acc[1][r] += u0*a1.x + u1*a1.y + u2*a1.z + u3*a1.w;
                acc[2][r] += u0*a2.x + u1*a2.y + u2*a2.z + u3*a2.w;
            }
        }
#pragma unroll
        for (int j = 0; j < 3; ++j){
            float bb = __ldg(&b_ih[t + j*256]);
#pragma unroll
            for (int r = 0; r < 4; ++r) sgi[r][t + j*256] = acc[j][r] + bb;
        }
    }

    // 4. gh = slots_prev @ W_hh^T + b_hh
    {
        float acc[3][4] = {};
        const float4* w0 = reinterpret_cast<const float4*>(W_hh + (size_t)(t      )*DD);
        const float4* w1 = reinterpret_cast<const float4*>(W_hh + (size_t)(t + 256)*DD);
        const float4* w2 = reinterpret_cast<const float4*>(W_hh + (size_t)(t + 512)*DD);
#pragma unroll 4
        for (int k4 = 0; k4 < 64; ++k4){
            float4 a0 = __ldg(&w0[k4]);
            float4 a1 = __ldg(&w1[k4]);
            float4 a2 = __ldg(&w2[k4]);
            int k = 4*k4;
#pragma unroll
            for (int r = 0; r < 4; ++r){
                float u0 = sprev[r][k], u1 = sprev[r][k+1], u2 = sprev[r][k+2], u3 = sprev[r][k+3];
                acc[0][r] += u0*a0.x + u1*a0.y + u2*a0.z + u3*a0.w;
                acc[1][r] += u0*a1.x + u1*a1.y + u2*a1.z + u3*a1.w;
                acc[2][r] += u0*a2.x + u1*a2.y + u2*a2.z + u3*a2.w;
            }
        }
#pragma unroll
        for (int j = 0; j < 3; ++j){
            float bb = __ldg(&b_hh[t + j*256]);
#pragma unroll
            for (int r = 0; r < 4; ++r) sgh[r][t + j*256] = acc[j][r] + bb;
        }
    }
    __syncthreads();

    // 5. GRU cell + residual
    float vnew[4];
#pragma unroll
    for (int r = 0; r < 4; ++r){
        float ir = sgi[r][t], iz = sgi[r][t+256], inn = sgi[r][t+512];
        float hr = sgh[r][t], hz = sgh[r][t+256], hn  = sgh[r][t+512];
        float rr = 1.f / (1.f + expf(-(ir + hr)));
        float zz = 1.f / (1.f + expf(-(iz + hz)));
        float nn = tanhf(inn + rr*hn);
        float h  = sprev[r][t];
        vnew[r]  = h + (1.f - zz)*nn + zz*h;
    }

    // 6. LN(vnew)
    float lnv[4];
    block_ln4(vnew, lnv, lng, lnb, t);
#pragma unroll
    for (int r = 0; r < 4; ++r) sln[r][t] = lnv[r];
    __syncthreads();

    // 7. hidden = relu(sln @ W1^T + b1)
    {
        const float4* wrow = reinterpret_cast<const float4*>(W1 + (size_t)t*DD);
        float a0=0.f,a1=0.f,a2=0.f,a3=0.f;
#pragma unroll 8
        for (int k4 = 0; k4 < 64; ++k4){
            float4 wv = __ldg(&wrow[k4]);
            int k = 4*k4;
            a0 += sln[0][k]*wv.x + sln[0][k+1]*wv.y + sln[0][k+2]*wv.z + sln[0][k+3]*wv.w;
            a1 += sln[1][k]*wv.x + sln[1][k+1]*wv.y + sln[1][k+2]*wv.z + sln[1][k+3]*wv.w;
            a2 += sln[2][k]*wv.x + sln[2][k+1]*wv.y + sln[2][k+2]*wv.z + sln[2][k+3]*wv.w;
            a3 += sln[3][k]*wv.x + sln[3][k+1]*wv.y + sln[3][k+2]*wv.z + sln[3][k+3]*wv.w;
        }
        float bb = __ldg(&b1[t]);
        shid[0][t] = fmaxf(a0 + bb, 0.f);
        shid[1][t] = fmaxf(a1 + bb, 0.f);
        shid[2][t] = fmaxf(a2 + bb, 0.f);
        shid[3][t] = fmaxf(a3 + bb, 0.f);
    }
    __syncthreads();

    // 8. out = vnew + hidden @ W2^T + b2
    {
        const float4* wrow = reinterpret_cast<const float4*>(W2 + (size_t)t*DD);
        float a0=0.f,a1=0.f,a2=0.f,a3=0.f;
#pragma unroll 8
        for (int k4 = 0; k4 < 64; ++k4){
            float4 wv = __ldg(&wrow[k4]);
            int k = 4*k4;
            a0 += shid[0][k]*wv.x + shid[0][k+1]*wv.y + shid[0][k+2]*wv.z + shid[0][k+3]*wv.w;
            a1 += shid[1][k]*wv.x + shid[1][k+1]*wv.y + shid[1][k+2]*wv.z + shid[1][k+3]*wv.w;
            a2 += shid[2][k]*wv.x + shid[2][k+1]*wv.y + shid[2][k+2]*wv.z + shid[2][k+3]*wv.w;
            a3 += shid[3][k]*wv.x + shid[3][k+1]*wv.y + shid[3][k+2]*wv.z + shid[3][k+3]*wv.w;
        }
        float bb = __ldg(&b2[t]);
        dst[(size_t)(r0+0)*DD + t] = vnew[0] + a0 + bb;
        dst[(size_t)(r0+1)*DD + t] = vnew[1] + a1 + bb;
        dst[(size_t)(r0+2)*DD + t] = vnew[2] + a2 + bb;
        dst[(size_t)(r0+3)*DD + t] = vnew[3] + a3 + bb;
    }
}

// ------------------------- host launcher -------------------------
extern "C" void kernel_launch(void* const* d_in, const int* in_sizes, int n_in,
                              void* d_out, int out_size)
{
    const float* inputs = (const float*)d_in[0];
    const float* noise  = (const float*)d_in[1];
    const float* s_mu   = (const float*)d_in[2];
    const float* s_sig  = (const float*)d_in[3];
    const float* Wq = (const float*)d_in[4];  const float* bq = (const float*)d_in[5];
    const float* Wk = (const float*)d_in[6];  /* bk = d_in[7] : dead (softmax shift-invariance) */
    const float* Wv = (const float*)d_in[8];  const float* bv = (const float*)d_in[9];
    const float* W_ih = (const float*)d_in[10]; const float* b_ih = (const float*)d_in[11];
    const float* W_hh = (const float*)d_in[12]; const float* b_hh = (const float*)d_in[13];
    const float* W1 = (const float*)d_in[14]; const float* b1 = (const float*)d_in[15];
    const float* W2 = (const float*)d_in[16]; const float* b2 = (const float*)d_in[17];
    const float* lnsg = (const float*)d_in[18]; const float* lnsb = (const float*)d_in[19];
    const float* lnmg = (const float*)d_in[20]; const float* lnmb = (const float*)d_in[21];
    float* out = (float*)d_out;
    (void)in_sizes; (void)n_in; (void)out_size;

    float *slots, *qW, *upart, *mbuf, *lbuf;
    cudaGetSymbolAddress((void**)&slots, g_slots);
    cudaGetSymbolAddress((void**)&qW,    g_qW);
    cudaGetSymbolAddress((void**)&upart, g_upart);
    cudaGetSymbolAddress((void**)&mbuf,  g_m);
    cudaGetSymbolAddress((void**)&lbuf,  g_l);

    dim3 gBN(BB, NCHUNK);

    init_slots_kernel<<<ROWS, 256>>>(noise, s_mu, s_sig, slots);

    for (int it = 0; it < 3; ++it){
        pre_kernel<<<ROWS/4, 256>>>(slots, lnsg, lnsb, Wq, bq, Wk, qW);
        attn_kernel<<<gBN, 256>>>(qW, inputs, upart, mbuf, lbuf);
        float* dst = (it == 2) ? out : slots;
        post_kernel<<<ROWS/4, 256>>>(upart, mbuf, lbuf, Wv, bv, W_ih, b_ih, W_hh, b_hh,
                                     lnmg, lnmb, W1, b1, W2, b2, slots, dst);
    }
}